// round 15
// baseline (speedup 1.0000x reference)
#include <cuda_runtime.h>
#include <cuda_fp16.h>
#include <cstdint>

// Problem constants
constexpr int Mdim = 4096, Kdim = 4096, Ndim = 4096, Gsz = 128;

constexpr int BM = 128, BN = 64, BK = 64;
constexpr int THREADS = 128;
constexpr int BKP  = 72;   // A row pad (halfs) -> 144B pitch (36w%32=4, conflict-free)
constexpr int RAWP = 80;   // raw W row pad (bytes): 20w%32 -> 8 distinct groups, conflict-free

// Shared memory layout (bytes), 2 pipeline stages
constexpr int A_STG    = BM * BKP * 2;            // 18432
constexpr int RAW_STG  = BN * RAWP;               // 5120
constexpr int SC_STG   = 256;                     // 64 halfs (padded)
constexpr int SM_A     = 0;
constexpr int SM_RAW   = 2 * A_STG;               // 36864
constexpr int SM_SC    = SM_RAW + 2 * RAW_STG;    // 47104
constexpr int SMEM_BYTES = SM_SC + 2 * SC_STG;    // 47616  (x4 CTAs = 190.5KB)

// Device-global scratch (allocation-guard safe)
__device__ uint8_t g_wq8[(size_t)Ndim * Kdim];          // 16 MB, [N][K], permuted v2
__device__ __half  g_a16[(size_t)Mdim * Kdim];          // 32 MB fp16 activations
__device__ __half  g_s16[(size_t)(Kdim / Gsz) * Ndim];  //  1 MB fp16 scales

__device__ __forceinline__ uint32_t smem_u32(const void* p) {
    return (uint32_t)__cvta_generic_to_shared(p);
}
#define CP_ASYNC16(dst, src) \
    asm volatile("cp.async.cg.shared.global [%0], [%1], 16;\n" ::"r"(dst), "l"(src))
#define CP_COMMIT() asm volatile("cp.async.commit_group;\n" ::)

// ---------------------------------------------------------------------------
// Pre-pass 1: int32 [K][N] -> uint8 TRANSPOSED [N][K], permutation v2.
// Per 32-k chunk, byte order (u32 index cg = q*2 + g, q=quad lane, g=k-group):
//   bytes [g*16 + q*2, +1, g*16 + q*2 + 8, +9]
// so lane q's fragment bytes for BOTH 16-k groups are one contiguous 8B (LDS.64).
// ---------------------------------------------------------------------------
__global__ void pack_wq_t_kernel(const int* __restrict__ wq) {
    __shared__ uint8_t tile[32][36];
    int tid = threadIdx.x;
    int tx = tid & 31, ty = tid >> 5;           // 32 x 8
    int bn = blockIdx.x * 32, bk = blockIdx.y * 32;
#pragma unroll
    for (int i = 0; i < 4; i++) {
        int k = ty + i * 8;
        tile[tx][k] = (uint8_t)wq[(size_t)(bk + k) * Ndim + bn + tx];
    }
    __syncthreads();
    int r = tid >> 3, cg = tid & 7;             // 32 rows x 8 u32 each
    int q = cg >> 1, g = cg & 1;                // quad lane, 16-k group
    int s0 = g * 16 + q * 2;
    uchar4 o;
    o.x = tile[r][s0 + 0]; o.y = tile[r][s0 + 1];
    o.z = tile[r][s0 + 8]; o.w = tile[r][s0 + 9];
    *(uchar4*)&g_wq8[(size_t)(bn + r) * Kdim + bk + cg * 4] = o;
}

// Pre-pass 2: fp32 (widened fp16) -> fp16; exact round-trip
__global__ void cvt_f32_to_f16_kernel(const float* __restrict__ src,
                                      __half* __restrict__ dst) {
    size_t i = (size_t)blockIdx.x * blockDim.x + threadIdx.x;
    float4 v = ((const float4*)src)[i];
    ((half2*)dst)[i * 2 + 0] = __floats2half2_rn(v.x, v.y);
    ((half2*)dst)[i * 2 + 1] = __floats2half2_rn(v.z, v.w);
}

// ---------------------------------------------------------------------------
// W4A16 GEMM: 4 small CTAs/SM so each SMSP hosts warps from 4 independent
// barrier domains (stall decoupling); register-direct B dequant, LDS.64.
// ---------------------------------------------------------------------------
__device__ __forceinline__ void issue_tile(uint32_t sbase, int m0, int n0,
                                           int tid, int t) {
    const int stg = t & 1;
    const int k0 = t * BK;
    // A tile: 128 rows x 128B = 8 16B-chunks per row = 1024 chunks, 8/thread
#pragma unroll
    for (int c = 0; c < 8; c++) {
        int chunk = c * THREADS + tid;
        int row = chunk >> 3, kc = chunk & 7;
        uint32_t dst = sbase + SM_A + stg * A_STG + row * (BKP * 2) + kc * 16;
        CP_ASYNC16(dst, &g_a16[(size_t)(m0 + row) * Kdim + k0 + kc * 8]);
    }
    // Raw W tile (u8, [N][K]): 64 rows x 64B = 4 16B-chunks per row = 256 chunks
#pragma unroll
    for (int c = 0; c < 2; c++) {
        int chunk = c * THREADS + tid;
        int row = chunk >> 2, ck = chunk & 3;
        uint32_t dst = sbase + SM_RAW + stg * RAW_STG + row * RAWP + ck * 16;
        CP_ASYNC16(dst, &g_wq8[(size_t)(n0 + row) * Kdim + k0 + ck * 16]);
    }
    // scales for this tile's k-group (group = t/2 since BK = Gsz/2): 64 halfs
    if (tid < 8) {
        uint32_t dst = sbase + SM_SC + stg * SC_STG + tid * 16;
        CP_ASYNC16(dst, &g_s16[(size_t)(t >> 1) * Ndim + n0 + tid * 8]);
    }
    CP_COMMIT();
}

__global__ __launch_bounds__(THREADS, 4)
void gemm_w4a16_kernel(float* __restrict__ C) {
    extern __shared__ char smem[];
    const uint32_t sbase = smem_u32(smem);
    const int tid = threadIdx.x, wid = tid >> 5, lane = tid & 31;

    // Block swizzle: supertiles of 8 m-tiles x 64 n-tiles
    const int tiles_n = Ndim / BN;            // 64
    const int GROUP_M = 8;
    int bid = blockIdx.x;
    int grp = bid / (GROUP_M * tiles_n), rem = bid % (GROUP_M * tiles_n);
    const int m0 = (grp * GROUP_M + rem % GROUP_M) * BM;
    const int n0 = (rem / GROUP_M) * BN;

    float acc[4][4][4];
#pragma unroll
    for (int i = 0; i < 4; i++)
#pragma unroll
        for (int j = 0; j < 4; j++)
#pragma unroll
            for (int r = 0; r < 4; r++) acc[i][j][r] = 0.0f;

    const int warp_m = (wid >> 1) * 64;  // 2 warps along M, 64 rows each
    const int warp_n = (wid & 1) * 32;   // 2 warps along N, 32 cols each

    issue_tile(sbase, m0, n0, tid, 0);

    const int nTiles = Kdim / BK;  // 64

    for (int t = 0; t < nTiles; ++t) {
        const int stg = t & 1;
        asm volatile("cp.async.wait_group 0;\n" ::);
        __syncthreads();
        if (t + 1 < nTiles) issue_tile(sbase, m0, n0, tid, t + 1);

        const char* Abuf = smem + SM_A + stg * A_STG;
        const char* Rawb = smem + SM_RAW + stg * RAW_STG;
        const half* Sc   = (const half*)(smem + SM_SC + stg * SC_STG);

        // Per-thread scale (and -1024*scale) for each of the 4 n8 fragments
        half2 sv[4], sb[4];
#pragma unroll
        for (int nj = 0; nj < 4; nj++) {
            half s = Sc[warp_n + nj * 8 + (lane >> 2)];
            sv[nj] = __half2half2(s);
            half nb = __hmul(s, __float2half_rn(-1024.0f));  // exact (power of 2)
            sb[nj] = __half2half2(nb);
        }
        // Base pointer: lane's 8 fragment bytes per 32-k chunk are contiguous
        const char* bbase = Rawb + (size_t)(warp_n + (lane >> 2)) * RAWP + 8 * (lane & 3);

        // Preload B raw words for first 32-k chunk
        uint2 bw[4];
#pragma unroll
        for (int nj = 0; nj < 4; nj++)
            bw[nj] = *(const uint2*)(bbase + (size_t)nj * 8 * RAWP);

#pragma unroll
        for (int kkp = 0; kkp < BK; kkp += 32) {
            // Prefetch next chunk's B raw words (hidden behind 32 MMAs)
            uint2 bwn[4];
            if (kkp + 32 < BK) {
#pragma unroll
                for (int nj = 0; nj < 4; nj++)
                    bwn[nj] = *(const uint2*)(bbase + (size_t)nj * 8 * RAWP + kkp + 32);
            }
#pragma unroll
            for (int half_ = 0; half_ < 2; half_++) {
                const int kk = kkp + half_ * 16;
                // A fragments via ldmatrix
                uint32_t a[4][4];
#pragma unroll
                for (int mi = 0; mi < 4; mi++) {
                    int row = warp_m + mi * 16 + (lane & 15);
                    int col = kk + (lane >> 4) * 8;
                    uint32_t addr = smem_u32(Abuf + (size_t)row * (BKP * 2) + col * 2);
                    asm volatile(
                        "ldmatrix.sync.aligned.m8n8.x4.shared.b16 {%0,%1,%2,%3}, [%4];\n"
                        : "=r"(a[mi][0]), "=r"(a[mi][1]), "=r"(a[mi][2]), "=r"(a[mi][3])
                        : "r"(addr));
                }
                // B fragments from registers: 2 PRMT + 2 HFMA2 per nj
                uint32_t b0[4], b1[4];
#pragma unroll
                for (int nj = 0; nj < 4; nj++) {
                    uint32_t w = half_ ? bw[nj].y : bw[nj].x;
                    uint32_t x0 = __byte_perm(w, 0x64006400u, 0x5150);
                    uint32_t x1 = __byte_perm(w, 0x64006400u, 0x5352);
                    half2 w0 = __hfma2(*(half2*)&x0, sv[nj], sb[nj]);
                    half2 w1 = __hfma2(*(half2*)&x1, sv[nj], sb[nj]);
                    b0[nj] = *(uint32_t*)&w0;
                    b1[nj] = *(uint32_t*)&w1;
                }
#pragma unroll
                for (int mi = 0; mi < 4; mi++) {
#pragma unroll
                    for (int nj = 0; nj < 4; nj++) {
                        asm volatile(
                            "mma.sync.aligned.m16n8k16.row.col.f32.f16.f16.f32 "
                            "{%0,%1,%2,%3}, {%4,%5,%6,%7}, {%8,%9}, {%0,%1,%2,%3};\n"
                            : "+f"(acc[mi][nj][0]), "+f"(acc[mi][nj][1]),
                              "+f"(acc[mi][nj][2]), "+f"(acc[mi][nj][3])
                            : "r"(a[mi][0]), "r"(a[mi][1]), "r"(a[mi][2]), "r"(a[mi][3]),
                              "r"(b0[nj]), "r"(b1[nj]));
                    }
                }
            }
#pragma unroll
            for (int nj = 0; nj < 4; nj++) bw[nj] = bwn[nj];
        }
    }

    // Epilogue: fp32 acc -> round through fp16 (mimic .astype(float16)) -> fp32 out
    const int r  = lane >> 2;
    const int c2 = (lane & 3) * 2;
#pragma unroll
    for (int mi = 0; mi < 4; mi++) {
#pragma unroll
        for (int nj = 0; nj < 4; nj++) {
            int row = m0 + warp_m + mi * 16 + r;
            int col = n0 + warp_n + nj * 8 + c2;
            float2 lo = make_float2(__half2float(__float2half_rn(acc[mi][nj][0])),
                                    __half2float(__float2half_rn(acc[mi][nj][1])));
            float2 hi = make_float2(__half2float(__float2half_rn(acc[mi][nj][2])),
                                    __half2float(__float2half_rn(acc[mi][nj][3])));
            *(float2*)&C[(size_t)row * Ndim + col] = lo;
            *(float2*)&C[(size_t)(row + 8) * Ndim + col] = hi;
        }
    }
}

// ---------------------------------------------------------------------------
// kernel_launch
// Inputs (fp16 widened to fp32 by harness):
//   d_in[0]=a fp32 [M,K], d_in[1]=w_q int32 [K,N], d_in[2]=scale fp32 [K/G,N]
// Output: fp32 [M,N]
// ---------------------------------------------------------------------------
extern "C" void kernel_launch(void* const* d_in, const int* in_sizes, int n_in,
                              void* d_out, int out_size) {
    const float* a  = (const float*)d_in[0];
    const int*   wq = (const int*)d_in[1];
    const float* s  = (const float*)d_in[2];
    float* out = (float*)d_out;

    cudaFuncSetAttribute(gemm_w4a16_kernel,
                         cudaFuncAttributeMaxDynamicSharedMemorySize, SMEM_BYTES);

    __half* a16_ptr;
    __half* s16_ptr;
    cudaGetSymbolAddress((void**)&a16_ptr, g_a16);
    cudaGetSymbolAddress((void**)&s16_ptr, g_s16);

    pack_wq_t_kernel<<<dim3(Ndim / 32, Kdim / 32), 256>>>(wq);
    cvt_f32_to_f16_kernel<<<(int)(((size_t)Mdim * Kdim) / 4 / 256), 256>>>(a, a16_ptr);
    cvt_f32_to_f16_kernel<<<(int)(((size_t)(Kdim / Gsz) * Ndim) / 4 / 256), 256>>>(s, s16_ptr);

    const int grid = (Mdim / BM) * (Ndim / BN);  // 2048
    gemm_w4a16_kernel<<<grid, THREADS, SMEM_BYTES>>>(out);
}

// round 16
// speedup vs baseline: 1.0615x; 1.0615x over previous
#include <cuda_runtime.h>
#include <cuda_fp16.h>
#include <cstdint>

// Problem constants
constexpr int Mdim = 4096, Kdim = 4096, Ndim = 4096, Gsz = 128;

constexpr int BM = 128, BN = 128, BK = 128;
constexpr int THREADS = 256;
constexpr int BKP  = 136;  // A row pad (halfs) -> 272B pitch
constexpr int RAWP = 160;  // raw W row pad (bytes): 40 words = 8 mod 32 -> LDS.64 conflict-free

// Shared memory layout (bytes), 2 pipeline stages
constexpr int A_STG    = BM * BKP * 2;            // 34816
constexpr int RAW_STG  = BN * RAWP;               // 20480
constexpr int SC_STG   = BN * 2;                  // 256
constexpr int SM_A     = 0;
constexpr int SM_RAW   = 2 * A_STG;               // 69632
constexpr int SM_SC    = SM_RAW + 2 * RAW_STG;    // 110592
constexpr int SMEM_BYTES = SM_SC + 2 * SC_STG;    // 111104 (x2 CTAs = 222.2KB)

// Device-global scratch (allocation-guard safe)
__device__ uint8_t g_wq8[(size_t)Ndim * Kdim];          // 16 MB, [N][K], permuted v2
__device__ __half  g_a16[(size_t)Mdim * Kdim];          // 32 MB fp16 activations
__device__ __half  g_s16[(size_t)(Kdim / Gsz) * Ndim];  //  1 MB fp16 scales

__device__ __forceinline__ uint32_t smem_u32(const void* p) {
    return (uint32_t)__cvta_generic_to_shared(p);
}
#define CP_ASYNC16(dst, src) \
    asm volatile("cp.async.cg.shared.global [%0], [%1], 16;\n" ::"r"(dst), "l"(src))
#define CP_COMMIT() asm volatile("cp.async.commit_group;\n" ::)

#define LDMATRIX_X4(frag, addr) \
    asm volatile("ldmatrix.sync.aligned.m8n8.x4.shared.b16 {%0,%1,%2,%3}, [%4];\n" \
        : "=r"((frag)[0]), "=r"((frag)[1]), "=r"((frag)[2]), "=r"((frag)[3]) \
        : "r"(addr))

// ---------------------------------------------------------------------------
// Pre-pass 1: int32 [K][N] -> uint8 TRANSPOSED [N][K], permutation v2.
// Per 32-k chunk, byte order (u32 index cg = q*2 + g, q=quad lane, g=k-group):
//   bytes [g*16 + q*2, +1, g*16 + q*2 + 8, +9]
// so lane q's fragment bytes for BOTH 16-k groups are one contiguous 8B (LDS.64).
// ---------------------------------------------------------------------------
__global__ void pack_wq_t_kernel(const int* __restrict__ wq) {
    __shared__ uint8_t tile[32][36];
    int tid = threadIdx.x;
    int tx = tid & 31, ty = tid >> 5;           // 32 x 8
    int bn = blockIdx.x * 32, bk = blockIdx.y * 32;
#pragma unroll
    for (int i = 0; i < 4; i++) {
        int k = ty + i * 8;
        tile[tx][k] = (uint8_t)wq[(size_t)(bk + k) * Ndim + bn + tx];
    }
    __syncthreads();
    int r = tid >> 3, cg = tid & 7;             // 32 rows x 8 u32 each
    int q = cg >> 1, g = cg & 1;                // quad lane, 16-k group
    int s0 = g * 16 + q * 2;
    uchar4 o;
    o.x = tile[r][s0 + 0]; o.y = tile[r][s0 + 1];
    o.z = tile[r][s0 + 8]; o.w = tile[r][s0 + 9];
    *(uchar4*)&g_wq8[(size_t)(bn + r) * Kdim + bk + cg * 4] = o;
}

// Pre-pass 2: fp32 (widened fp16) -> fp16; exact round-trip
__global__ void cvt_f32_to_f16_kernel(const float* __restrict__ src,
                                      __half* __restrict__ dst) {
    size_t i = (size_t)blockIdx.x * blockDim.x + threadIdx.x;
    float4 v = ((const float4*)src)[i];
    ((half2*)dst)[i * 2 + 0] = __floats2half2_rn(v.x, v.y);
    ((half2*)dst)[i * 2 + 1] = __floats2half2_rn(v.z, v.w);
}

// ---------------------------------------------------------------------------
// W4A16 GEMM, mma.sync path; A-fragment software pipeline (paired mi), B via
// LDS.64 register double-buffer + PRMT/HFMA2 register-direct dequant.
// ---------------------------------------------------------------------------
__device__ __forceinline__ void issue_tile(uint32_t sbase, int m0, int n0,
                                           int tid, int t) {
    const int stg = t & 1;
    const int k0 = t * BK;
    // A tile: 128 rows x 16 16B-chunks = 2048 chunks, 8/thread
#pragma unroll
    for (int c = 0; c < 8; c++) {
        int chunk = c * THREADS + tid;
        int row = chunk >> 4, kc = chunk & 15;
        uint32_t dst = sbase + SM_A + stg * A_STG + row * (BKP * 2) + kc * 16;
        CP_ASYNC16(dst, &g_a16[(size_t)(m0 + row) * Kdim + k0 + kc * 8]);
    }
    // Raw W tile (u8, [N][K]): 128 rows x 8 16B-chunks = 1024 chunks, 4/thread
#pragma unroll
    for (int c = 0; c < 4; c++) {
        int chunk = c * THREADS + tid;
        int row = chunk >> 3, ck = chunk & 7;
        uint32_t dst = sbase + SM_RAW + stg * RAW_STG + row * RAWP + ck * 16;
        CP_ASYNC16(dst, &g_wq8[(size_t)(n0 + row) * Kdim + k0 + ck * 16]);
    }
    // scales for this k-group (BK == Gsz): 128 halfs = 16 x 16B
    if (tid < 16) {
        uint32_t dst = sbase + SM_SC + stg * SC_STG + tid * 16;
        CP_ASYNC16(dst, &g_s16[(size_t)t * Ndim + n0 + tid * 8]);
    }
    CP_COMMIT();
}

__global__ __launch_bounds__(THREADS, 2)
void gemm_w4a16_kernel(float* __restrict__ C) {
    extern __shared__ char smem[];
    const uint32_t sbase = smem_u32(smem);
    const int tid = threadIdx.x, wid = tid >> 5, lane = tid & 31;

    // Block swizzle: supertiles of 8 m-tiles x 32 n-tiles
    const int tiles_n = Ndim / BN;            // 32
    const int GROUP_M = 8;
    int bid = blockIdx.x;
    int grp = bid / (GROUP_M * tiles_n), rem = bid % (GROUP_M * tiles_n);
    const int m0 = (grp * GROUP_M + rem % GROUP_M) * BM;
    const int n0 = (rem / GROUP_M) * BN;

    float acc[4][4][4];
#pragma unroll
    for (int i = 0; i < 4; i++)
#pragma unroll
        for (int j = 0; j < 4; j++)
#pragma unroll
            for (int r = 0; r < 4; r++) acc[i][j][r] = 0.0f;

    const int warp_m = (wid >> 2) * 64;  // 2 warps along M
    const int warp_n = (wid & 3) * 32;   // 4 warps along N

    issue_tile(sbase, m0, n0, tid, 0);

    const int nTiles = Kdim / BK;  // 32

    for (int t = 0; t < nTiles; ++t) {
        const int stg = t & 1;
        asm volatile("cp.async.wait_group 0;\n" ::);
        __syncthreads();
        if (t + 1 < nTiles) issue_tile(sbase, m0, n0, tid, t + 1);

        const char* Abuf = smem + SM_A + stg * A_STG;
        const char* Rawb = smem + SM_RAW + stg * RAW_STG;
        const half* Sc   = (const half*)(smem + SM_SC + stg * SC_STG);

        // Per-thread scale (and -1024*scale) for each of the 4 n8 fragments
        half2 sv[4], sb[4];
#pragma unroll
        for (int nj = 0; nj < 4; nj++) {
            half s = Sc[warp_n + nj * 8 + (lane >> 2)];
            sv[nj] = __half2half2(s);
            half nb = __hmul(s, __float2half_rn(-1024.0f));  // exact (power of 2)
            sb[nj] = __half2half2(nb);
        }
        // Base pointer: lane's 8 fragment bytes per 32-k chunk are contiguous
        const char* bbase = Rawb + (size_t)(warp_n + (lane >> 2)) * RAWP + 8 * (lane & 3);

        // A-fragment smem addressing (fixed per thread)
        const int arow = lane & 15;
        const int acol8 = (lane >> 4) * 8;

        // Preload B raw words for first 32-k chunk
        uint2 bw[4];
#pragma unroll
        for (int nj = 0; nj < 4; nj++)
            bw[nj] = *(const uint2*)(bbase + (size_t)nj * 8 * RAWP);

        // Preload A fragments for mi-pair 0 (mi = 0,1) at kk = 0
        uint32_t aP[2][4];
#pragma unroll
        for (int mi = 0; mi < 2; mi++) {
            uint32_t addr = smem_u32(Abuf +
                (size_t)(warp_m + mi * 16 + arow) * (BKP * 2) + acol8 * 2);
            LDMATRIX_X4(aP[mi], addr);
        }

#pragma unroll
        for (int kkp = 0; kkp < BK; kkp += 32) {
            // Prefetch next chunk's B raw words (hidden behind 32 MMAs)
            uint2 bwn[4];
            if (kkp + 32 < BK) {
#pragma unroll
                for (int nj = 0; nj < 4; nj++)
                    bwn[nj] = *(const uint2*)(bbase + (size_t)nj * 8 * RAWP + kkp + 32);
            }
#pragma unroll
            for (int half_ = 0; half_ < 2; half_++) {
                const int kk = kkp + half_ * 16;
                // Load A fragments for mi-pair 1 (mi = 2,3) at kk — latency
                // hidden by the pair-0 MMAs below
                uint32_t aQ[2][4];
#pragma unroll
                for (int mi = 0; mi < 2; mi++) {
                    uint32_t addr = smem_u32(Abuf +
                        (size_t)(warp_m + (2 + mi) * 16 + arow) * (BKP * 2) +
                        (kk + acol8) * 2);
                    LDMATRIX_X4(aQ[mi], addr);
                }
                // B fragments from registers: 2 PRMT + 2 HFMA2 per nj
                uint32_t b0[4], b1[4];
#pragma unroll
                for (int nj = 0; nj < 4; nj++) {
                    uint32_t w = half_ ? bw[nj].y : bw[nj].x;
                    uint32_t x0 = __byte_perm(w, 0x64006400u, 0x5150);
                    uint32_t x1 = __byte_perm(w, 0x64006400u, 0x5352);
                    half2 w0 = __hfma2(*(half2*)&x0, sv[nj], sb[nj]);
                    half2 w1 = __hfma2(*(half2*)&x1, sv[nj], sb[nj]);
                    b0[nj] = *(uint32_t*)&w0;
                    b1[nj] = *(uint32_t*)&w1;
                }
                // MMA pair 0 (mi = 0,1) with previously-loaded aP
#pragma unroll
                for (int mi = 0; mi < 2; mi++) {
#pragma unroll
                    for (int nj = 0; nj < 4; nj++) {
                        asm volatile(
                            "mma.sync.aligned.m16n8k16.row.col.f32.f16.f16.f32 "
                            "{%0,%1,%2,%3}, {%4,%5,%6,%7}, {%8,%9}, {%0,%1,%2,%3};\n"
                            : "+f"(acc[mi][nj][0]), "+f"(acc[mi][nj][1]),
                              "+f"(acc[mi][nj][2]), "+f"(acc[mi][nj][3])
                            : "r"(aP[mi][0]), "r"(aP[mi][1]), "r"(aP[mi][2]), "r"(aP[mi][3]),
                              "r"(b0[nj]), "r"(b1[nj]));
                    }
                }
                // Preload pair-0 A fragments for the NEXT 16-k step — latency
                // hidden by the pair-1 MMAs below
                const int kn = kk + 16;
                uint32_t aPn[2][4];
                if (kn < BK) {
#pragma unroll
                    for (int mi = 0; mi < 2; mi++) {
                        uint32_t addr = smem_u32(Abuf +
                            (size_t)(warp_m + mi * 16 + arow) * (BKP * 2) +
                            (kn + acol8) * 2);
                        LDMATRIX_X4(aPn[mi], addr);
                    }
                }
                // MMA pair 1 (mi = 2,3) with aQ
#pragma unroll
                for (int mi = 0; mi < 2; mi++) {
#pragma unroll
                    for (int nj = 0; nj < 4; nj++) {
                        asm volatile(
                            "mma.sync.aligned.m16n8k16.row.col.f32.f16.f16.f32 "
                            "{%0,%1,%2,%3}, {%4,%5,%6,%7}, {%8,%9}, {%0,%1,%2,%3};\n"
                            : "+f"(acc[2 + mi][nj][0]), "+f"(acc[2 + mi][nj][1]),
                              "+f"(acc[2 + mi][nj][2]), "+f"(acc[2 + mi][nj][3])
                            : "r"(aQ[mi][0]), "r"(aQ[mi][1]), "r"(aQ[mi][2]), "r"(aQ[mi][3]),
                              "r"(b0[nj]), "r"(b1[nj]));
                    }
                }
                if (kn < BK) {
#pragma unroll
                    for (int mi = 0; mi < 2; mi++)
#pragma unroll
                        for (int r2 = 0; r2 < 4; r2++) aP[mi][r2] = aPn[mi][r2];
                }
            }
#pragma unroll
            for (int nj = 0; nj < 4; nj++) bw[nj] = bwn[nj];
        }
        // Preload for next tile happens after the next barrier (aP reloaded there)
        if (t + 1 < nTiles) {
            // nothing: aP re-initialized at top of next iteration's section
        }
    }

    // Epilogue: fp32 acc -> round through fp16 (mimic .astype(float16)) -> fp32 out
    const int r  = lane >> 2;
    const int c2 = (lane & 3) * 2;
#pragma unroll
    for (int mi = 0; mi < 4; mi++) {
#pragma unroll
        for (int nj = 0; nj < 4; nj++) {
            int row = m0 + warp_m + mi * 16 + r;
            int col = n0 + warp_n + nj * 8 + c2;
            float2 lo = make_float2(__half2float(__float2half_rn(acc[mi][nj][0])),
                                    __half2float(__float2half_rn(acc[mi][nj][1])));
            float2 hi = make_float2(__half2float(__float2half_rn(acc[mi][nj][2])),
                                    __half2float(__float2half_rn(acc[mi][nj][3])));
            *(float2*)&C[(size_t)row * Ndim + col] = lo;
            *(float2*)&C[(size_t)(row + 8) * Ndim + col] = hi;
        }
    }
}

// ---------------------------------------------------------------------------
// kernel_launch
// Inputs (fp16 widened to fp32 by harness):
//   d_in[0]=a fp32 [M,K], d_in[1]=w_q int32 [K,N], d_in[2]=scale fp32 [K/G,N]
// Output: fp32 [M,N]
// ---------------------------------------------------------------------------
extern "C" void kernel_launch(void* const* d_in, const int* in_sizes, int n_in,
                              void* d_out, int out_size) {
    const float* a  = (const float*)d_in[0];
    const int*   wq = (const int*)d_in[1];
    const float* s  = (const float*)d_in[2];
    float* out = (float*)d_out;

    cudaFuncSetAttribute(gemm_w4a16_kernel,
                         cudaFuncAttributeMaxDynamicSharedMemorySize, SMEM_BYTES);

    __half* a16_ptr;
    __half* s16_ptr;
    cudaGetSymbolAddress((void**)&a16_ptr, g_a16);
    cudaGetSymbolAddress((void**)&s16_ptr, g_s16);

    pack_wq_t_kernel<<<dim3(Ndim / 32, Kdim / 32), 256>>>(wq);
    cvt_f32_to_f16_kernel<<<(int)(((size_t)Mdim * Kdim) / 4 / 256), 256>>>(a, a16_ptr);
    cvt_f32_to_f16_kernel<<<(int)(((size_t)(Kdim / Gsz) * Ndim) / 4 / 256), 256>>>(s, s16_ptr);

    const int grid = (Mdim / BM) * (Ndim / BN);  // 1024
    gemm_w4a16_kernel<<<grid, THREADS, SMEM_BYTES>>>(out);
}